// round 1
// baseline (speedup 1.0000x reference)
#include <cuda_runtime.h>

// Problem constants
#define B_    32
#define CIN_  64
#define Hh    32
#define Ww    32
#define CO_   64
#define KK    7
#define G_    8
#define PAD_  3
#define CPG_  8
#define HP    38            // padded side
#define NPIX  (HP*HP)       // 1444

// Scratch (no cudaMalloc allowed)
__device__ float g_q[B_ * Hh * Ww * CO_];        // [b][hw][o]   8.4 MB
__device__ float g_k[B_ * NPIX * CO_];           // [b][pp][o]  11.8 MB
__device__ float g_v[B_ * NPIX * CO_];           // [b][pp][o]  11.8 MB
__device__ float g_wT[3 * CIN_ * CO_];           // [m][c][o]

// ---------------------------------------------------------------------------
// Transpose weights (o,c) -> (c,o) so projection kernels get conflict-free
// smem fills and uniform float4 reads.
// ---------------------------------------------------------------------------
__global__ void transpose_w_kernel(const float* __restrict__ wq,
                                   const float* __restrict__ wk,
                                   const float* __restrict__ wv) {
    const float* src = (blockIdx.x == 0) ? wq : (blockIdx.x == 1 ? wk : wv);
    float* dst = g_wT + blockIdx.x * 4096;
    for (int idx = threadIdx.x; idx < 4096; idx += blockDim.x) {
        int o = idx >> 6, c = idx & 63;
        dst[c * 64 + o] = src[idx];
    }
}

// ---------------------------------------------------------------------------
// Q projection: q[b][hw][o] = sum_c x[b][c][hw] * Wq[o][c]
// CTA: 128 pixels x 64 out-ch, 256 threads, thread = 8 oc x 4 px (32 acc)
// ---------------------------------------------------------------------------
__global__ __launch_bounds__(256) void proj_q_kernel(const float* __restrict__ x) {
    __shared__ float w_s[4096];      // [c][o]
    __shared__ float x_s[8192];      // [c][px]
    const int b  = blockIdx.y;
    const int p0 = blockIdx.x * 128;

    for (int idx = threadIdx.x; idx < 4096; idx += 256) w_s[idx] = g_wT[idx];
    const float* xb = x + b * (CIN_ * Hh * Ww);
    for (int idx = threadIdx.x; idx < 8192; idx += 256) {
        int c = idx >> 7, px = idx & 127;
        x_s[idx] = xb[c * 1024 + p0 + px];
    }
    __syncthreads();

    const int pxg = threadIdx.x & 31;   // 4-pixel group
    const int ocg = threadIdx.x >> 5;   // 8-channel group
    float acc[4][8];
#pragma unroll
    for (int p = 0; p < 4; p++)
#pragma unroll
        for (int j = 0; j < 8; j++) acc[p][j] = 0.f;

    const float4* x4 = (const float4*)x_s;
    const float4* w4 = (const float4*)w_s;
#pragma unroll 8
    for (int c = 0; c < 64; c++) {
        float4 xv = x4[c * 32 + pxg];
        float4 wa = w4[c * 16 + ocg * 2];
        float4 wb = w4[c * 16 + ocg * 2 + 1];
        float xs[4] = {xv.x, xv.y, xv.z, xv.w};
        float ws[8] = {wa.x, wa.y, wa.z, wa.w, wb.x, wb.y, wb.z, wb.w};
#pragma unroll
        for (int p = 0; p < 4; p++)
#pragma unroll
            for (int j = 0; j < 8; j++) acc[p][j] += xs[p] * ws[j];
    }

#pragma unroll
    for (int p = 0; p < 4; p++) {
        int pix = p0 + pxg * 4 + p;
        float* op = g_q + (size_t)(b * 1024 + pix) * 64 + ocg * 8;
        ((float4*)op)[0] = make_float4(acc[p][0], acc[p][1], acc[p][2], acc[p][3]);
        ((float4*)op)[1] = make_float4(acc[p][4], acc[p][5], acc[p][6], acc[p][7]);
    }
}

// ---------------------------------------------------------------------------
// Padded projection for K (sel=1) or V (sel=2) over the 38x38 padded domain.
// Out-of-image positions project zero (matches pad-then-project).
// ---------------------------------------------------------------------------
__global__ __launch_bounds__(256) void proj_pad_kernel(const float* __restrict__ x,
                                                       int sel) {
    __shared__ float w_s[4096];      // [c][o]
    __shared__ float x_s[8192];      // [c][px]
    const int b  = blockIdx.y;
    const int p0 = blockIdx.x * 128;
    const float* wt   = g_wT + sel * 4096;
    float*       outb = (sel == 1) ? g_k : g_v;

    for (int idx = threadIdx.x; idx < 4096; idx += 256) w_s[idx] = wt[idx];
    const float* xb = x + b * (CIN_ * Hh * Ww);
    for (int idx = threadIdx.x; idx < 8192; idx += 256) {
        int c = idx >> 7, px = idx & 127;
        int pp = p0 + px;
        float val = 0.f;
        if (pp < NPIX) {
            int y  = pp / HP;
            int xx = pp - y * HP;
            if (y >= PAD_ && y < PAD_ + Hh && xx >= PAD_ && xx < PAD_ + Ww)
                val = xb[c * 1024 + (y - PAD_) * Ww + (xx - PAD_)];
        }
        x_s[idx] = val;
    }
    __syncthreads();

    const int pxg = threadIdx.x & 31;
    const int ocg = threadIdx.x >> 5;
    float acc[4][8];
#pragma unroll
    for (int p = 0; p < 4; p++)
#pragma unroll
        for (int j = 0; j < 8; j++) acc[p][j] = 0.f;

    const float4* x4 = (const float4*)x_s;
    const float4* w4 = (const float4*)w_s;
#pragma unroll 8
    for (int c = 0; c < 64; c++) {
        float4 xv = x4[c * 32 + pxg];
        float4 wa = w4[c * 16 + ocg * 2];
        float4 wb = w4[c * 16 + ocg * 2 + 1];
        float xs[4] = {xv.x, xv.y, xv.z, xv.w};
        float ws[8] = {wa.x, wa.y, wa.z, wa.w, wb.x, wb.y, wb.z, wb.w};
#pragma unroll
        for (int p = 0; p < 4; p++)
#pragma unroll
            for (int j = 0; j < 8; j++) acc[p][j] += xs[p] * ws[j];
    }

#pragma unroll
    for (int p = 0; p < 4; p++) {
        int pix = p0 + pxg * 4 + p;
        if (pix < NPIX) {
            float* op = outb + (size_t)(b * NPIX + pix) * 64 + ocg * 8;
            ((float4*)op)[0] = make_float4(acc[p][0], acc[p][1], acc[p][2], acc[p][3]);
            ((float4*)op)[1] = make_float4(acc[p][4], acc[p][5], acc[p][6], acc[p][7]);
        }
    }
}

// ---------------------------------------------------------------------------
// Attention: CTA = (b, g, 8-row tile). Thread = one output pixel.
// k/v tile staged in smem as two 4-channel planes [pix][4] -> aligned,
// conflict-free LDS.128 per (i,j).
// ---------------------------------------------------------------------------
#define TROWS 8
#define TPIX  (532)   // (TROWS + KK - 1) * HP = 14*38

__global__ __launch_bounds__(256) void attn_kernel(const float* __restrict__ rel_h,
                                                   const float* __restrict__ rel_w,
                                                   const float* __restrict__ cur,
                                                   float* __restrict__ out) {
    const int h0 = blockIdx.x * TROWS;
    const int g  = blockIdx.y;
    const int b  = blockIdx.z;

    __shared__ __align__(16) float k_s[2 * TPIX * 4];
    __shared__ __align__(16) float v_s[2 * TPIX * 4];
    float4* ks4 = (float4*)k_s;
    float4* vs4 = (float4*)v_s;

    const float4* gk4 = (const float4*)g_k + (size_t)(b * NPIX + h0 * HP) * 16 + g * 2;
    const float4* gv4 = (const float4*)g_v + (size_t)(b * NPIX + h0 * HP) * 16 + g * 2;
    for (int idx = threadIdx.x; idx < 2 * TPIX; idx += 256) {
        int pp = idx >> 1, c4 = idx & 1;
        ks4[c4 * TPIX + pp] = gk4[pp * 16 + c4];
        vs4[c4 * TPIX + pp] = gv4[pp * 16 + c4];
    }
    __syncthreads();

    const int r = threadIdx.x >> 5;        // local row
    const int w = threadIdx.x & 31;        // column
    const int h = h0 + r;

    const float4* qp = (const float4*)(g_q + (size_t)(b * 1024 + h * 32 + w) * 64 + g * 8);
    float4 qa = qp[0], qb = qp[1];
    float q[8] = {qa.x, qa.y, qa.z, qa.w, qb.x, qb.y, qb.z, qb.w};

    // rel positional term folded into scores: depends only on i (g<4) or j (g>=4)
    float rel[7];
    if (g < 4) {
        const float* rh = rel_h + g * 56;
#pragma unroll
        for (int i = 0; i < 7; i++) {
            float s = 0.f;
#pragma unroll
            for (int c = 0; c < 8; c++) s += q[c] * rh[c * 7 + i];
            rel[i] = s;
        }
    } else {
        const float* rw = rel_w + (g - 4) * 56;
#pragma unroll
        for (int j = 0; j < 7; j++) {
            float s = 0.f;
#pragma unroll
            for (int c = 0; c < 8; c++) s += q[c] * rw[c * 7 + j];
            rel[j] = s;
        }
    }

    float sc[49];
#pragma unroll
    for (int i = 0; i < 7; i++)
#pragma unroll
        for (int j = 0; j < 7; j++) sc[i * 7 + j] = (g < 4) ? rel[i] : rel[j];

#pragma unroll
    for (int i = 0; i < 7; i++) {
        int base = (r + i) * HP + w;
#pragma unroll
        for (int j = 0; j < 7; j++) {
            int pix = base + j;
            float4 ka = ks4[pix];
            float4 kb = ks4[TPIX + pix];
            sc[i * 7 + j] += q[0] * ka.x + q[1] * ka.y + q[2] * ka.z + q[3] * ka.w
                           + q[4] * kb.x + q[5] * kb.y + q[6] * kb.z + q[7] * kb.w;
        }
    }

    // softmax over 49
    float m = sc[0];
#pragma unroll
    for (int s = 1; s < 49; s++) m = fmaxf(m, sc[s]);
    float sum = 0.f;
#pragma unroll
    for (int s = 0; s < 49; s++) { sc[s] = __expf(sc[s] - m); sum += sc[s]; }

    float oa[8];
#pragma unroll
    for (int c = 0; c < 8; c++) oa[c] = 0.f;
#pragma unroll
    for (int i = 0; i < 7; i++) {
        int base = (r + i) * HP + w;
#pragma unroll
        for (int j = 0; j < 7; j++) {
            int pix = base + j;
            float p = sc[i * 7 + j];
            float4 va = vs4[pix];
            float4 vb = vs4[TPIX + pix];
            oa[0] += p * va.x; oa[1] += p * va.y; oa[2] += p * va.z; oa[3] += p * va.w;
            oa[4] += p * vb.x; oa[5] += p * vb.y; oa[6] += p * vb.z; oa[7] += p * vb.w;
        }
    }

    float inv = 1.f / sum;

    // adaptive ring mask: mask[g,h,w]
    int rr = min(h, 31 - h);
    int lo = (h <= 31 - h) ? rr : rr + 1;
    int hi = 31 - rr;
    float om = ((float)(rr - 15) + cur[g] * 16.f) / 3.f + 1.f;
    om = fminf(fmaxf(om, 0.f), 1.f);
    float mk = (w >= lo && w <= hi) ? om : 1.f;
    float scal = inv * mk;

    float* op = out + (size_t)(b * 64 + g * 8) * 1024 + h * 32 + w;
#pragma unroll
    for (int c = 0; c < 8; c++) op[c * 1024] = oa[c] * scal;
}

// ---------------------------------------------------------------------------
extern "C" void kernel_launch(void* const* d_in, const int* in_sizes, int n_in,
                              void* d_out, int out_size) {
    const float* x  = (const float*)d_in[0];
    const float* wq = (const float*)d_in[1];
    const float* wk = (const float*)d_in[2];
    const float* wv = (const float*)d_in[3];
    const float* rh = (const float*)d_in[4];
    const float* rw = (const float*)d_in[5];
    const float* cv = (const float*)d_in[6];
    float* out = (float*)d_out;

    transpose_w_kernel<<<3, 256>>>(wq, wk, wv);
    proj_q_kernel<<<dim3(8, B_), 256>>>(x);
    proj_pad_kernel<<<dim3(12, B_), 256>>>(x, 1);   // K
    proj_pad_kernel<<<dim3(12, B_), 256>>>(x, 2);   // V
    attn_kernel<<<dim3(Hh / TROWS, G_, B_), 256>>>(rh, rw, cv, out);
}

// round 3
// speedup vs baseline: 1.2477x; 1.2477x over previous
#include <cuda_runtime.h>

// Problem constants
#define B_    32
#define CIN_  64
#define Hh    32
#define Ww    32
#define CO_   64
#define KK    7
#define G_    8
#define PAD_  3
#define HP    38            // padded side
#define NPIX  (HP*HP)       // 1444

// Scratch (no cudaMalloc allowed)
__device__ float g_q[B_ * Hh * Ww * CO_];        // [b][hw][o]
__device__ float g_k[B_ * NPIX * CO_];           // [b][pp][o]
__device__ float g_v[B_ * NPIX * CO_];           // [b][pp][o]
__device__ float g_wT[3 * CIN_ * CO_];           // [m][c][o]

// ---- packed fp32 helpers (sm_103a FFMA2 path) ------------------------------
#define PACKF(out, lo, hi) \
    asm("mov.b64 %0, {%1, %2};" : "=l"(out) : "f"(lo), "f"(hi))
#define UNPACKF(lo, hi, in) \
    asm("mov.b64 {%0, %1}, %2;" : "=f"(lo), "=f"(hi) : "l"(in))
#define FFMA2(d, a, b) \
    asm("fma.rn.f32x2 %0, %1, %2, %0;" : "+l"(d) : "l"(a), "l"(b))

// ---------------------------------------------------------------------------
// Transpose weights (o,c) -> (c,o)
// ---------------------------------------------------------------------------
__global__ void transpose_w_kernel(const float* __restrict__ wq,
                                   const float* __restrict__ wk,
                                   const float* __restrict__ wv) {
    const float* src = (blockIdx.x == 0) ? wq : (blockIdx.x == 1 ? wk : wv);
    float* dst = g_wT + blockIdx.x * 4096;
    for (int idx = threadIdx.x; idx < 4096; idx += blockDim.x) {
        int o = idx >> 6, c = idx & 63;
        dst[c * 64 + o] = src[idx];
    }
}

// ---------------------------------------------------------------------------
// Fused Q/K/V projection over the padded 38x38 domain.
// CTA: 128 padded pixels. 128 threads, thread = 8 px x 8 oc, f32x2 packed acc.
// Three passes (Q, K, V) reuse the staged x tile; weights reloaded per pass.
// Border pixels project zero (pad-then-project equivalence).
// ---------------------------------------------------------------------------
__global__ __launch_bounds__(128) void proj_qkv_kernel(const float* __restrict__ x) {
    __shared__ __align__(16) float x_s[8192];   // [c][px] 64 x 128
    __shared__ __align__(16) float w_s[4096];   // [c][o]
    const int b  = blockIdx.y;
    const int p0 = blockIdx.x * 128;
    const float* xb = x + (size_t)b * (CIN_ * Hh * Ww);

    for (int idx = threadIdx.x; idx < 8192; idx += 128) {
        int c = idx >> 7, px = idx & 127;
        int pp = p0 + px;
        float val = 0.f;
        if (pp < NPIX) {
            int y  = pp / HP;
            int xx = pp - y * HP;
            if (y >= PAD_ && y < PAD_ + Hh && xx >= PAD_ && xx < PAD_ + Ww)
                val = xb[c * 1024 + (y - PAD_) * Ww + (xx - PAD_)];
        }
        x_s[idx] = val;
    }

    const int pxg = threadIdx.x & 15;   // 16 groups of 8 pixels
    const int ocg = threadIdx.x >> 4;   // 8 groups of 8 out-ch
    const float4* x4 = (const float4*)x_s;
    const ulonglong2* w2 = (const ulonglong2*)w_s;   // 16 per 64-float row

    for (int m = 0; m < 3; m++) {
        __syncthreads();   // protect w_s reuse
        for (int idx = threadIdx.x; idx < 4096; idx += 128)
            w_s[idx] = g_wT[m * 4096 + idx];
        __syncthreads();

        unsigned long long acc[8][4];
#pragma unroll
        for (int p = 0; p < 8; p++)
#pragma unroll
            for (int j = 0; j < 4; j++) acc[p][j] = 0ULL;

#pragma unroll 8
        for (int c = 0; c < 64; c++) {
            float4 xa = x4[c * 32 + pxg * 2];
            float4 xc = x4[c * 32 + pxg * 2 + 1];
            ulonglong2 wa = w2[c * 16 + ocg * 2];        // FIX: 16 u128/row
            ulonglong2 wb = w2[c * 16 + ocg * 2 + 1];
            float xs[8] = {xa.x, xa.y, xa.z, xa.w, xc.x, xc.y, xc.z, xc.w};
#pragma unroll
            for (int p = 0; p < 8; p++) {
                unsigned long long xp;
                PACKF(xp, xs[p], xs[p]);
                FFMA2(acc[p][0], xp, wa.x);
                FFMA2(acc[p][1], xp, wa.y);
                FFMA2(acc[p][2], xp, wb.x);
                FFMA2(acc[p][3], xp, wb.y);
            }
        }

        float* dst = (m == 0) ? g_q : (m == 1 ? g_k : g_v);
#pragma unroll
        for (int p = 0; p < 8; p++) {
            int pix = p0 + pxg * 8 + p;
            if (pix >= NPIX) continue;
            float o0, o1, o2, o3, o4, o5, o6, o7;
            UNPACKF(o0, o1, acc[p][0]);
            UNPACKF(o2, o3, acc[p][1]);
            UNPACKF(o4, o5, acc[p][2]);
            UNPACKF(o6, o7, acc[p][3]);
            float* op;
            if (m == 0) {
                int y  = pix / HP;
                int xx = pix - y * HP;
                if (y < PAD_ || y >= PAD_ + Hh || xx < PAD_ || xx >= PAD_ + Ww) continue;
                op = g_q + (size_t)(b * 1024 + (y - PAD_) * Ww + (xx - PAD_)) * 64 + ocg * 8;
            } else {
                op = dst + (size_t)(b * NPIX + pix) * 64 + ocg * 8;
            }
            ((float4*)op)[0] = make_float4(o0, o1, o2, o3);
            ((float4*)op)[1] = make_float4(o4, o5, o6, o7);
        }
    }
}

// ---------------------------------------------------------------------------
// Attention: CTA = (b, g, 8-row tile). 128 threads, thread = 2 adjacent rows
// at one column (shares the 8x7 k/v window between the two rows).
// ---------------------------------------------------------------------------
#define TROWS 8
#define TPIX  532   // (TROWS + KK - 1) * HP = 14*38

__global__ __launch_bounds__(128) void attn_kernel(const float* __restrict__ rel_h,
                                                   const float* __restrict__ rel_w,
                                                   const float* __restrict__ cur,
                                                   float* __restrict__ out) {
    const int h0 = blockIdx.x * TROWS;
    const int g  = blockIdx.y;
    const int b  = blockIdx.z;

    __shared__ __align__(16) float k_s[2 * TPIX * 4];
    __shared__ __align__(16) float v_s[2 * TPIX * 4];
    float4* ks4 = (float4*)k_s;
    float4* vs4 = (float4*)v_s;

    const float4* gk4 = (const float4*)g_k + (size_t)(b * NPIX + h0 * HP) * 16 + g * 2;
    const float4* gv4 = (const float4*)g_v + (size_t)(b * NPIX + h0 * HP) * 16 + g * 2;
    for (int idx = threadIdx.x; idx < 2 * TPIX; idx += 128) {
        int pp = idx >> 1, c4 = idx & 1;
        ks4[c4 * TPIX + pp] = gk4[pp * 16 + c4];
        vs4[c4 * TPIX + pp] = gv4[pp * 16 + c4];
    }
    __syncthreads();

    const int rp = threadIdx.x >> 5;       // row-pair 0..3
    const int w  = threadIdx.x & 31;       // column
    const int hA = h0 + rp * 2;
    const int hB = hA + 1;

    // q for both rows
    const float4* qPA = (const float4*)(g_q + (size_t)(b * 1024 + hA * 32 + w) * 64 + g * 8);
    const float4* qPB = (const float4*)(g_q + (size_t)(b * 1024 + hB * 32 + w) * 64 + g * 8);
    float4 a0 = qPA[0], a1 = qPA[1];
    float4 b0 = qPB[0], b1 = qPB[1];
    float qA[8] = {a0.x, a0.y, a0.z, a0.w, a1.x, a1.y, a1.z, a1.w};
    float qB[8] = {b0.x, b0.y, b0.z, b0.w, b1.x, b1.y, b1.z, b1.w};
    unsigned long long qAp[4], qBp[4];
#pragma unroll
    for (int c = 0; c < 4; c++) {
        PACKF(qAp[c], qA[2 * c], qA[2 * c + 1]);
        PACKF(qBp[c], qB[2 * c], qB[2 * c + 1]);
    }

    // rel positional term: depends only on i (g<4) or j (g>=4)
    float relA[7], relB[7];
    {
        const float* rb = (g < 4) ? (rel_h + g * 56) : (rel_w + (g - 4) * 56);
#pragma unroll
        for (int t = 0; t < 7; t++) {
            float sA = 0.f, sB = 0.f;
#pragma unroll
            for (int c = 0; c < 8; c++) {
                float rv = rb[c * 7 + t];
                sA += qA[c] * rv;
                sB += qB[c] * rv;
            }
            relA[t] = sA; relB[t] = sB;
        }
    }

    const ulonglong2* ks2 = (const ulonglong2*)k_s;
    const ulonglong2* vs2 = (const ulonglong2*)v_s;

    float scA[49], scB[49];
#pragma unroll
    for (int i = 0; i < 8; i++) {
        int rowbase = (rp * 2 + i) * HP + w;
#pragma unroll
        for (int j = 0; j < 7; j++) {
            int pix = rowbase + j;
            ulonglong2 ka = ks2[pix];
            ulonglong2 kb = ks2[TPIX + pix];
            if (i < 7) {
                unsigned long long t;
                PACKF(t, (g < 4) ? relA[i] : relA[j], 0.f);
                FFMA2(t, ka.x, qAp[0]); FFMA2(t, ka.y, qAp[1]);
                FFMA2(t, kb.x, qAp[2]); FFMA2(t, kb.y, qAp[3]);
                float lo, hi; UNPACKF(lo, hi, t);
                scA[i * 7 + j] = lo + hi;
            }
            if (i > 0) {
                unsigned long long t;
                PACKF(t, (g < 4) ? relB[i - 1] : relB[j], 0.f);
                FFMA2(t, ka.x, qBp[0]); FFMA2(t, ka.y, qBp[1]);
                FFMA2(t, kb.x, qBp[2]); FFMA2(t, kb.y, qBp[3]);
                float lo, hi; UNPACKF(lo, hi, t);
                scB[(i - 1) * 7 + j] = lo + hi;
            }
        }
    }

    // softmax per row
    float mA = scA[0], mB = scB[0];
#pragma unroll
    for (int s = 1; s < 49; s++) { mA = fmaxf(mA, scA[s]); mB = fmaxf(mB, scB[s]); }
    float sumA = 0.f, sumB = 0.f;
#pragma unroll
    for (int s = 0; s < 49; s++) {
        scA[s] = __expf(scA[s] - mA); sumA += scA[s];
        scB[s] = __expf(scB[s] - mB); sumB += scB[s];
    }

    unsigned long long oA[4] = {0, 0, 0, 0}, oB[4] = {0, 0, 0, 0};
#pragma unroll
    for (int i = 0; i < 8; i++) {
        int rowbase = (rp * 2 + i) * HP + w;
#pragma unroll
        for (int j = 0; j < 7; j++) {
            int pix = rowbase + j;
            ulonglong2 va = vs2[pix];
            ulonglong2 vb = vs2[TPIX + pix];
            if (i < 7) {
                float p = scA[i * 7 + j];
                unsigned long long pp; PACKF(pp, p, p);
                FFMA2(oA[0], pp, va.x); FFMA2(oA[1], pp, va.y);
                FFMA2(oA[2], pp, vb.x); FFMA2(oA[3], pp, vb.y);
            }
            if (i > 0) {
                float p = scB[(i - 1) * 7 + j];
                unsigned long long pp; PACKF(pp, p, p);
                FFMA2(oB[0], pp, va.x); FFMA2(oB[1], pp, va.y);
                FFMA2(oB[2], pp, vb.x); FFMA2(oB[3], pp, vb.y);
            }
        }
    }

    const float cg = cur[g];
    // row A
    {
        float inv = 1.f / sumA;
        int rr = min(hA, 31 - hA);
        int lo = (hA <= 31 - hA) ? rr : rr + 1;
        int hi = 31 - rr;
        float om = ((float)(rr - 15) + cg * 16.f) / 3.f + 1.f;
        om = fminf(fmaxf(om, 0.f), 1.f);
        float mk = (w >= lo && w <= hi) ? om : 1.f;
        float scal = inv * mk;
        float o0, o1, o2, o3, o4, o5, o6, o7;
        UNPACKF(o0, o1, oA[0]); UNPACKF(o2, o3, oA[1]);
        UNPACKF(o4, o5, oA[2]); UNPACKF(o6, o7, oA[3]);
        float* op = out + (size_t)(b * 64 + g * 8) * 1024 + hA * 32 + w;
        op[0]        = o0 * scal; op[1024]     = o1 * scal;
        op[2 * 1024] = o2 * scal; op[3 * 1024] = o3 * scal;
        op[4 * 1024] = o4 * scal; op[5 * 1024] = o5 * scal;
        op[6 * 1024] = o6 * scal; op[7 * 1024] = o7 * scal;
    }
    // row B
    {
        float inv = 1.f / sumB;
        int rr = min(hB, 31 - hB);
        int lo = (hB <= 31 - hB) ? rr : rr + 1;
        int hi = 31 - rr;
        float om = ((float)(rr - 15) + cg * 16.f) / 3.f + 1.f;
        om = fminf(fmaxf(om, 0.f), 1.f);
        float mk = (w >= lo && w <= hi) ? om : 1.f;
        float scal = inv * mk;
        float o0, o1, o2, o3, o4, o5, o6, o7;
        UNPACKF(o0, o1, oB[0]); UNPACKF(o2, o3, oB[1]);
        UNPACKF(o4, o5, oB[2]); UNPACKF(o6, o7, oB[3]);
        float* op = out + (size_t)(b * 64 + g * 8) * 1024 + hB * 32 + w;
        op[0]        = o0 * scal; op[1024]     = o1 * scal;
        op[2 * 1024] = o2 * scal; op[3 * 1024] = o3 * scal;
        op[4 * 1024] = o4 * scal; op[5 * 1024] = o5 * scal;
        op[6 * 1024] = o6 * scal; op[7 * 1024] = o7 * scal;
    }
}

// ---------------------------------------------------------------------------
extern "C" void kernel_launch(void* const* d_in, const int* in_sizes, int n_in,
                              void* d_out, int out_size) {
    const float* x  = (const float*)d_in[0];
    const float* wq = (const float*)d_in[1];
    const float* wk = (const float*)d_in[2];
    const float* wv = (const float*)d_in[3];
    const float* rh = (const float*)d_in[4];
    const float* rw = (const float*)d_in[5];
    const float* cv = (const float*)d_in[6];
    float* out = (float*)d_out;

    transpose_w_kernel<<<3, 256>>>(wq, wk, wv);
    proj_qkv_kernel<<<dim3(12, B_), 128>>>(x);
    attn_kernel<<<dim3(Hh / TROWS, G_, B_), 128>>>(rh, rw, cv, out);
}